// round 13
// baseline (speedup 1.0000x reference)
#include <cuda_runtime.h>
#include <cuda_fp16.h>
#include <cuda_bf16.h>
#include <math.h>
#include <stdint.h>

// ===========================================================================
// Problem constants
// ===========================================================================
#define D_IN   256
#define H_HID  128
#define TILE_M 128
#define KHALF  128
#define N_MAX  302080
#define K1_THREADS 256
#define K4_BLOCKS 8192
#define K4_THREADS 64

#define XS_STRIDE 136     // fp16 elems per x-smem row (128 + 8 pad)
#define WS_STRIDE 264     // fp16 elems per W1t-smem row (256 + 8 pad)

// SMEM layout (byte offsets into dynamic smem)
#define SM_PS    0                           // 384 floats (3 n-warps x 128 rows)
#define SM_SMAX  1536                        // 1 float (+pad)
#define SM_B1    1568                        // 128 floats
#define SM_W2    2080                        // 128 floats
#define SM_XF    2592                        // fp16 x tile: 128*136*2 = 34816 B
#define SM_WHI   (SM_XF + 34816)             // 128*264*2 = 67584 B
#define SM_RAW   (SM_WHI + 67584)            // raw fp32 half-tile: 128*128*4 = 65536 B
#define SMEM_TOTAL (SM_RAW + 65536)          // ~170.5 KB

// Scratch (device globals: no allocation allowed)
__device__ float g_scores[N_MAX];   // scores, then exp(s-max) after k3
__device__ float g_stats[2];        // [0] = global max, [1] = sum of exp
__device__ int   g_batch64;         // 1 if batch buffer is int64, 0 if int32

// ===========================================================================
// Warp MMA + ldmatrix + cp.async (baseline PTX, sm_80+)
// ===========================================================================
__device__ __forceinline__ void mma_fp16(float* c,
                                         uint32_t a0, uint32_t a1,
                                         uint32_t a2, uint32_t a3,
                                         uint32_t b0, uint32_t b1)
{
    asm volatile(
        "mma.sync.aligned.m16n8k16.row.col.f32.f16.f16.f32 "
        "{%0,%1,%2,%3}, {%4,%5,%6,%7}, {%8,%9}, {%0,%1,%2,%3};"
        : "+f"(c[0]), "+f"(c[1]), "+f"(c[2]), "+f"(c[3])
        : "r"(a0), "r"(a1), "r"(a2), "r"(a3), "r"(b0), "r"(b1));
}

__device__ __forceinline__ void ldmatrix_x4(uint32_t* r, uint32_t addr)
{
    asm volatile(
        "ldmatrix.sync.aligned.m8n8.x4.shared.b16 {%0,%1,%2,%3}, [%4];"
        : "=r"(r[0]), "=r"(r[1]), "=r"(r[2]), "=r"(r[3]) : "r"(addr));
}

#define CP_ASYNC16(dst, src) \
    asm volatile("cp.async.cg.shared.global [%0], [%1], 16;" \
                 :: "r"(dst), "l"(src) : "memory")
#define CP_COMMIT()  asm volatile("cp.async.commit_group;" ::: "memory")
#define CP_WAIT0()   asm volatile("cp.async.wait_group 0;" ::: "memory")

__device__ void atomicMaxFloat(float* addr, float v)
{
    int* ai  = (int*)addr;
    int  old = *ai;
    while (__int_as_float(old) < v) {
        int assumed = old;
        old = atomicCAS(ai, assumed, __float_as_int(v));
        if (old == assumed) break;
    }
}

// ===========================================================================
// K0: zero output, init stats, detect batch dtype
// int64 layout: int-index N-1 (odd) is the HIGH word of an element -> 0.
// int32 layout: it's the last sorted batch id -> ~511 (nonzero).
// ===========================================================================
__global__ void k0_init(float* __restrict__ out, int out_size,
                        const int* __restrict__ batch_raw, int N)
{
    int idx = blockIdx.x * blockDim.x + threadIdx.x;
    int stride = gridDim.x * blockDim.x;
    for (int i = idx; i < out_size; i += stride) out[i] = 0.0f;
    if (idx == 0) {
        g_stats[0] = -1e30f;
        g_stats[1] = 0.0f;
        g_batch64 = (batch_raw[N - 1] == 0) ? 1 : 0;
    }
}

// ===========================================================================
// K1: scores = relu(x @ W1 + b1) @ W2, warp-mma fp16 (x fp16, W1 fp16).
// UNCHANGED (measured at/near its HMMA-throughput roofline in R9).
// ===========================================================================
extern __shared__ char k1s[];

__global__ __launch_bounds__(K1_THREADS, 1)
void k1_scores(const float* __restrict__ x,
               const float* __restrict__ W1,
               const float* __restrict__ b1,
               const float* __restrict__ W2,
               int N)
{
    int tid  = threadIdx.x;
    int wid  = tid >> 5;
    int lane = tid & 31;
    int g    = lane >> 2;     // group id 0..7
    int t    = lane & 3;      // thread-in-group 0..3
    int wm   = wid >> 2;      // 0..1  -> rows wm*64
    int wn   = wid & 3;       // 0..3  -> cols wn*32

    float*  ps   = (float*)(k1s + SM_PS);
    float*  smax = (float*)(k1s + SM_SMAX);
    float*  b1s  = (float*)(k1s + SM_B1);
    float*  W2s  = (float*)(k1s + SM_W2);
    __half* xf   = (__half*)(k1s + SM_XF);
    __half* whi  = (__half*)(k1s + SM_WHI);
    float*  raw  = (float*)(k1s + SM_RAW);

    uint32_t sbase = (uint32_t)__cvta_generic_to_shared(k1s);

    if (tid < H_HID) { b1s[tid] = b1[tid]; W2s[tid] = W2[tid]; }
    if (tid == 0) *smax = -1e30f;

    // --- Convert W1^T into whi fp16 smem (once). wT[n][k] = W1[k*H+n] ---
    for (int i = tid; i < D_IN * H_HID; i += K1_THREADS) {
        int n = i & 127;
        int k = i >> 7;
        whi[n * WS_STRIDE + k] = __float2half_rn(W1[k * H_HID + n]);
    }

    // --- ldmatrix per-lane address offsets (bytes, excluding k offset) ---
    int ri = lane & 7;        // row within 8x8 tile
    int q  = lane >> 3;       // quadrant 0..3
    int a_off[4];
#pragma unroll
    for (int mt = 0; mt < 4; mt++) {
        int row = wm * 64 + mt * 16 + ri + (q & 1) * 8;
        a_off[mt] = row * XS_STRIDE * 2 + ((q >> 1) * 8) * 2;
    }
    int b_off[2];
#pragma unroll
    for (int j = 0; j < 2; j++) {
        int nt = 2 * j + (q >> 1);
        int nrow = wn * 32 + nt * 8 + ri;
        b_off[j] = nrow * WS_STRIDE * 2 + ((q & 1) * 8) * 2;
    }

    int ntiles = (N + TILE_M - 1) / TILE_M;

    // issue cp.async for a half-tile into raw (16 chunks of 16B per thread)
    auto issue_raw = [&](int row0, int half) {
#pragma unroll
        for (int it = 0; it < (TILE_M * (KHALF / 4)) / K1_THREADS; it++) {
            int i  = it * K1_THREADS + tid;
            int r  = i >> 5;
            int c4 = i & 31;
            int gr = row0 + r;
            uint32_t dst = sbase + SM_RAW + (uint32_t)i * 16;
            if (gr < N) {
                const float* src = x + (size_t)gr * D_IN + half * KHALF + c4 * 4;
                CP_ASYNC16(dst, src);
            } else {
                *(float4*)(raw + i * 4) = make_float4(0.f, 0.f, 0.f, 0.f);
            }
        }
        CP_COMMIT();
    };

    // convert raw fp32 -> xf fp16 (each thread owns the same chunks it issued)
    auto convert = [&]() {
#pragma unroll
        for (int it = 0; it < (TILE_M * (KHALF / 4)) / K1_THREADS; it++) {
            int i  = it * K1_THREADS + tid;
            int r  = i >> 5;
            int c4 = i & 31;
            float4 v = *(const float4*)(raw + i * 4);
            __half2 h01 = __floats2half2_rn(v.x, v.y);
            __half2 h23 = __floats2half2_rn(v.z, v.w);
            *(uint2*)(xf + r * XS_STRIDE + c4 * 4) =
                make_uint2(*(uint32_t*)&h01, *(uint32_t*)&h23);
        }
    };

    // prologue: start loading first half-tile
    int tile = blockIdx.x;
    if (tile < ntiles) issue_raw(tile * TILE_M, 0);

    float lmax = -1e30f;

    for (; tile < ntiles; tile += gridDim.x) {
        int row0 = tile * TILE_M;

        float C[4][4][4];
#pragma unroll
        for (int mt = 0; mt < 4; mt++)
#pragma unroll
            for (int nt = 0; nt < 4; nt++)
#pragma unroll
                for (int qq = 0; qq < 4; qq++) C[mt][nt][qq] = 0.0f;

        for (int half = 0; half < 2; half++) {
            // raw[this half] arrived; previous MMA readers of xf are done
            CP_WAIT0();
            __syncthreads();
            convert();
            __syncthreads();   // xf visible to all warps (raw fully consumed)

            // start async load of the NEXT half (raw is free now)
            int ptile = (half == 0) ? tile : (tile + (int)gridDim.x);
            if (ptile < ntiles) issue_raw(ptile * TILE_M, half ^ 1);

            int kB0 = half * KHALF;

#pragma unroll 2
            for (int ks = 0; ks < 8; ks++) {
                int ka = ks * 16;
                int kb = kB0 + ka;

                uint32_t A[4][4];
#pragma unroll
                for (int mt = 0; mt < 4; mt++)
                    ldmatrix_x4(A[mt], sbase + SM_XF + a_off[mt] + ka * 2);

                uint32_t BH[2][4];
#pragma unroll
                for (int j = 0; j < 2; j++)
                    ldmatrix_x4(BH[j], sbase + SM_WHI + b_off[j] + kb * 2);

#pragma unroll
                for (int j = 0; j < 2; j++)
#pragma unroll
                    for (int jj = 0; jj < 2; jj++) {
                        int nt = 2 * j + jj;
                        uint32_t bh0 = BH[j][2 * jj], bh1 = BH[j][2 * jj + 1];
#pragma unroll
                        for (int mt = 0; mt < 4; mt++)
                            mma_fp16(C[mt][nt], A[mt][0], A[mt][1], A[mt][2], A[mt][3], bh0, bh1);
                    }
            }
        }

        // --- Epilogue: relu(h + b1) dot W2, quad reduce, cross-warp combine ---
        float pAv[4], pBv[4];
#pragma unroll
        for (int mt = 0; mt < 4; mt++) {
            float pa = 0.0f, pb = 0.0f;
#pragma unroll
            for (int nt = 0; nt < 4; nt++) {
                int c0 = wn * 32 + nt * 8 + 2 * t;
                float bb0 = b1s[c0], bb1 = b1s[c0 + 1];
                float ww0 = W2s[c0], ww1 = W2s[c0 + 1];
                float h;
                h = C[mt][nt][0] + bb0; h = h > 0.f ? h : 0.f; pa = fmaf(h, ww0, pa);
                h = C[mt][nt][1] + bb1; h = h > 0.f ? h : 0.f; pa = fmaf(h, ww1, pa);
                h = C[mt][nt][2] + bb0; h = h > 0.f ? h : 0.f; pb = fmaf(h, ww0, pb);
                h = C[mt][nt][3] + bb1; h = h > 0.f ? h : 0.f; pb = fmaf(h, ww1, pb);
            }
            pa += __shfl_xor_sync(0xffffffffu, pa, 1);
            pa += __shfl_xor_sync(0xffffffffu, pa, 2);
            pb += __shfl_xor_sync(0xffffffffu, pb, 1);
            pb += __shfl_xor_sync(0xffffffffu, pb, 2);
            pAv[mt] = pa; pBv[mt] = pb;
        }

        if (wn > 0 && t == 0) {
#pragma unroll
            for (int mt = 0; mt < 4; mt++) {
                int rA = wm * 64 + mt * 16 + g;
                ps[(wn - 1) * 128 + rA]     = pAv[mt];
                ps[(wn - 1) * 128 + rA + 8] = pBv[mt];
            }
        }
        __syncthreads();
        if (wn == 0 && t == 0) {
#pragma unroll
            for (int mt = 0; mt < 4; mt++) {
                int rA = wm * 64 + mt * 16 + g;
                float ta = pAv[mt] + ps[rA] + ps[128 + rA] + ps[256 + rA];
                float tb = pBv[mt] + ps[rA + 8] + ps[128 + rA + 8] + ps[256 + rA + 8];
                int gA = row0 + rA, gB = gA + 8;
                if (gA < N) { g_scores[gA] = ta; lmax = fmaxf(lmax, ta); }
                if (gB < N) { g_scores[gB] = tb; lmax = fmaxf(lmax, tb); }
            }
        }
        __syncthreads();   // ps consumed before next tile overwrites
    }

    // --- fold per-CTA max into global max ---
    if (wn == 0 && t == 0) atomicMaxFloat(smax, lmax);
    __syncthreads();
    if (tid == 0) atomicMaxFloat(&g_stats[0], *smax);
}

// ===========================================================================
// K3: u[i] = exp(s[i] - max) written in place; accumulate Z = sum u
// ===========================================================================
__global__ void k3_sumexp(int N)
{
    float gm = g_stats[0];
    float acc = 0.0f;
    int idx = blockIdx.x * blockDim.x + threadIdx.x;
    int stride = gridDim.x * blockDim.x;
    for (int i = idx; i < N; i += stride) {
        float u = expf(g_scores[i] - gm);
        g_scores[i] = u;
        acc += u;
    }
#pragma unroll
    for (int o = 16; o >= 1; o >>= 1)
        acc += __shfl_xor_sync(0xffffffffu, acc, o);
    __shared__ float s[8];
    int warp = threadIdx.x >> 5, lane = threadIdx.x & 31;
    if (lane == 0) s[warp] = acc;
    __syncthreads();
    if (warp == 0) {
        acc = (lane < (blockDim.x >> 5)) ? s[lane] : 0.0f;
#pragma unroll
        for (int o = 4; o >= 1; o >>= 1)
            acc += __shfl_xor_sync(0xffffffffu, acc, o);
        if (lane == 0) atomicAdd(&g_stats[1], acc);
    }
}

// ===========================================================================
// K4: pooled[batch[i], :] += x[i, :] * u[i] / Z   (batch sorted)
// 64 threads/block, 4 columns per thread via float4 loads (LDG.128):
// 4x fewer load instructions per byte, 4x fewer redundant scalar loads.
// Unroll x4 with front-batched independent loads.
// ===========================================================================
__device__ __forceinline__ int read_batch_i(const void* batch, int r, int is64)
{
    if (is64) return (int)((const long long*)batch)[r];
    return ((const int*)batch)[r];
}

__global__ __launch_bounds__(K4_THREADS)
void k4_pool(const float* __restrict__ x,
             const void* __restrict__ batch,
             float* __restrict__ out,
             int N, int out_size)
{
    int c = threadIdx.x * 4;     // first of 4 columns owned by this thread
    int is64 = g_batch64;
    float rz = 1.0f / g_stats[1];
    int nb    = gridDim.x;
    int chunk = (N + nb - 1) / nb;
    int r0 = blockIdx.x * chunk;
    int r1 = r0 + chunk;
    if (r1 > N) r1 = N;
    if (r0 >= r1) return;
    int nseg = out_size / D_IN;

    int cur = read_batch_i(batch, r0, is64);
    float ax = 0.f, ay = 0.f, az = 0.f, aw = 0.f;

#define FLUSH() do { \
        if ((unsigned)cur < (unsigned)nseg) { \
            float* o = out + (size_t)cur * D_IN + c; \
            atomicAdd(o + 0, ax); atomicAdd(o + 1, ay); \
            atomicAdd(o + 2, az); atomicAdd(o + 3, aw); \
        } \
        ax = ay = az = aw = 0.f; \
    } while (0)

    int r = r0;
    for (; r + 4 <= r1; r += 4) {
        // front-batched independent loads
        float4 xv[4];
        float  w[4];
        int    bb[4];
#pragma unroll
        for (int u = 0; u < 4; u++)
            xv[u] = *(const float4*)(x + (size_t)(r + u) * D_IN + c);
#pragma unroll
        for (int u = 0; u < 4; u++)
            w[u] = g_scores[r + u];
#pragma unroll
        for (int u = 0; u < 4; u++)
            bb[u] = read_batch_i(batch, r + u, is64);

#pragma unroll
        for (int u = 0; u < 4; u++) {
            if (bb[u] != cur) { FLUSH(); cur = bb[u]; }
            float wu = w[u] * rz;
            ax = fmaf(xv[u].x, wu, ax);
            ay = fmaf(xv[u].y, wu, ay);
            az = fmaf(xv[u].z, wu, az);
            aw = fmaf(xv[u].w, wu, aw);
        }
    }
    for (; r < r1; r++) {
        float4 xv = *(const float4*)(x + (size_t)r * D_IN + c);
        float wu  = g_scores[r] * rz;
        int b = read_batch_i(batch, r, is64);
        if (b != cur) { FLUSH(); cur = b; }
        ax = fmaf(xv.x, wu, ax);
        ay = fmaf(xv.y, wu, ay);
        az = fmaf(xv.z, wu, az);
        aw = fmaf(xv.w, wu, aw);
    }
    FLUSH();
#undef FLUSH
}

// ===========================================================================
// Launch
// ===========================================================================
extern "C" void kernel_launch(void* const* d_in, const int* in_sizes, int n_in,
                              void* d_out, int out_size)
{
    const float* x = (const float*)d_in[0];
    const void*  batch = d_in[1];
    int N = in_sizes[1];

    int iW1 = -1;
    for (int i = 2; i < n_in; i++)
        if (in_sizes[i] == D_IN * H_HID) { iW1 = i; break; }
    if (iW1 < 0) iW1 = 2;
    const float* W1 = (const float*)d_in[iW1];
    const float* b1 = (const float*)d_in[iW1 + 1];
    const float* W2 = (const float*)d_in[iW1 + 2];
    // b2 dropped: constant shift is softmax-invariant

    cudaFuncSetAttribute(k1_scores, cudaFuncAttributeMaxDynamicSharedMemorySize,
                         SMEM_TOTAL);

    k0_init<<<512, 256>>>((float*)d_out, out_size, (const int*)batch, N);
    k1_scores<<<148, K1_THREADS, SMEM_TOTAL>>>(x, W1, b1, W2, N);
    k3_sumexp<<<592, 256>>>(N);
    k4_pool<<<K4_BLOCKS, K4_THREADS>>>(x, batch, (float*)d_out, N, out_size);
}